// round 3
// baseline (speedup 1.0000x reference)
#include <cuda_runtime.h>

#define NN 1024
#define DD 128

// Scratch (device globals: allocation-free, graph-capture safe)
__device__ float g_PIB[NN * DD];   // pi + b1, row-major [i][d]
__device__ float g_PJT[DD * NN];   // pj transposed   [d][j]

// ---------------------------------------------------------------------------
// Kernel A: pi = z @ W1[:128] (+b1), pj = z @ W1[128:]  (stored transposed)
// 256 blocks x 128 threads; thread = output column d; 4 rows i per block.
// ---------------------------------------------------------------------------
__global__ void __launch_bounds__(128) prep_kernel(
    const float* __restrict__ z, const float* __restrict__ W1,
    const float* __restrict__ b1)
{
    __shared__ float zs[4][DD];
    const int d  = threadIdx.x;
    const int i0 = blockIdx.x * 4;

    #pragma unroll
    for (int ii = 0; ii < 4; ii++) zs[ii][d] = z[(i0 + ii) * DD + d];
    __syncthreads();

    float api[4] = {0.f, 0.f, 0.f, 0.f};
    float apj[4] = {0.f, 0.f, 0.f, 0.f};

    #pragma unroll 4
    for (int k = 0; k < DD; k++) {
        const float wpi = __ldg(&W1[k * DD + d]);
        const float wpj = __ldg(&W1[(DD + k) * DD + d]);
        #pragma unroll
        for (int ii = 0; ii < 4; ii++) {
            const float zz = zs[ii][k];
            api[ii] = fmaf(zz, wpi, api[ii]);
            apj[ii] = fmaf(zz, wpj, apj[ii]);
        }
    }

    const float bb = __ldg(&b1[d]);
    #pragma unroll
    for (int ii = 0; ii < 4; ii++) {
        g_PIB[(i0 + ii) * DD + d] = api[ii] + bb;
        g_PJT[d * NN + (i0 + ii)] = apj[ii];
    }
}

// ---------------------------------------------------------------------------
// Kernel B: q[i,j] = sum_d relu(PIB[i,d] + PJT[d,j]) * W2[d] + b2
// Block tile: 32 i x 64 j. Block (16,16): tx -> 4 consecutive j, ty -> 2 i.
// pi tile + W2 in smem (LDS.128 via 4-float row pad); pj read as float4 rows.
// ---------------------------------------------------------------------------
#define IT 32
#define JT 64

__global__ void __launch_bounds__(256) pair_kernel(
    const float* __restrict__ W2, const float* __restrict__ b2,
    float* __restrict__ out)
{
    __shared__ float pis[IT][DD + 4];   // +4 pad: keeps float4 alignment, spreads banks
    __shared__ float w2s[DD];

    const int tx  = threadIdx.x;        // 0..15 -> j quad
    const int ty  = threadIdx.y;        // 0..15 -> i pair
    const int tid = ty * 16 + tx;
    const int ib  = blockIdx.y * IT;
    const int jb  = blockIdx.x * JT;

    // Load pi tile (32x128 floats) cooperatively, coalesced
    for (int idx = tid; idx < IT * DD; idx += 256) {
        const int r = idx >> 7;
        const int c = idx & (DD - 1);
        pis[r][c] = g_PIB[(ib + r) * DD + c];
    }
    if (tid < DD) w2s[tid] = W2[tid];
    __syncthreads();

    const float bias2 = __ldg(b2);
    const int j0 = jb + tx * 4;
    const int r0 = ty * 2;

    float acc[2][4];
    #pragma unroll
    for (int r = 0; r < 2; r++)
        #pragma unroll
        for (int jj = 0; jj < 4; jj++) acc[r][jj] = 0.f;

    #pragma unroll 4
    for (int d4 = 0; d4 < DD / 4; d4++) {
        float wv[4], a0[4], a1[4];
        *(float4*)wv = *(const float4*)&w2s[d4 * 4];
        *(float4*)a0 = *(const float4*)&pis[r0][d4 * 4];
        *(float4*)a1 = *(const float4*)&pis[r0 + 1][d4 * 4];

        #pragma unroll
        for (int u = 0; u < 4; u++) {
            const int d = d4 * 4 + u;
            float bv[4];
            *(float4*)bv = __ldg((const float4*)(g_PJT + d * NN + j0));
            #pragma unroll
            for (int jj = 0; jj < 4; jj++) {
                float t0 = a0[u] + bv[jj];
                t0 = fmaxf(t0, 0.f);
                acc[0][jj] = fmaf(t0, wv[u], acc[0][jj]);
                float t1 = a1[u] + bv[jj];
                t1 = fmaxf(t1, 0.f);
                acc[1][jj] = fmaf(t1, wv[u], acc[1][jj]);
            }
        }
    }

    const int ig = ib + r0;
    #pragma unroll
    for (int r = 0; r < 2; r++) {
        float4 o;
        o.x = acc[r][0] + bias2;
        o.y = acc[r][1] + bias2;
        o.z = acc[r][2] + bias2;
        o.w = acc[r][3] + bias2;
        *(float4*)&out[(ig + r) * NN + j0] = o;
    }
}

// ---------------------------------------------------------------------------
// metadata order: z [1024*128], W1 [256*128], b1 [128], W2 [128], b2 [1]
// output: float32 [1024*1024]
// ---------------------------------------------------------------------------
extern "C" void kernel_launch(void* const* d_in, const int* in_sizes, int n_in,
                              void* d_out, int out_size)
{
    const float* z  = (const float*)d_in[0];
    const float* W1 = (const float*)d_in[1];
    const float* b1 = (const float*)d_in[2];
    const float* W2 = (const float*)d_in[3];
    const float* b2 = (const float*)d_in[4];
    float* out = (float*)d_out;

    prep_kernel<<<NN / 4, 128>>>(z, W1, b1);

    dim3 blk(16, 16);
    dim3 grd(NN / JT, NN / IT);
    pair_kernel<<<grd, blk>>>(W2, b2, out);
}

// round 4
// speedup vs baseline: 1.2303x; 1.2303x over previous
#include <cuda_runtime.h>

#define NN 1024
#define DD 128

// ---------------------------------------------------------------------------
// Device scratch (allocation-free)
// ---------------------------------------------------------------------------
__device__ float g_PIB [NN * DD];   // pi + b1, row-major [i][d]   (for ci)
__device__ float g_PIBT[DD * NN];   // pi + b1, transposed [d][i]  (for pair)
__device__ float g_PJ  [NN * DD];   // pj, row-major [j][d]        (for cj)
__device__ float g_PJT [DD * NN];   // pj, transposed [d][j]       (for pair)
__device__ float g_W2H [DD];        // 0.5 * W2
__device__ float g_ci  [NN];        // 0.5 * PIB[i,:] . W2
__device__ float g_cj  [NN];        // 0.5 * PJ[j,:]  . W2

// ---------------------------------------------------------------------------
// f32x2 packed helpers (sm_103a)
// ---------------------------------------------------------------------------
__device__ __forceinline__ unsigned long long pack2(float lo, float hi) {
    unsigned long long r;
    asm("mov.b64 %0, {%1, %2};" : "=l"(r) : "f"(lo), "f"(hi));
    return r;
}
__device__ __forceinline__ void unpack2(unsigned long long v, float& lo, float& hi) {
    asm("mov.b64 {%0, %1}, %2;" : "=f"(lo), "=f"(hi) : "l"(v));
}
__device__ __forceinline__ unsigned long long add2(unsigned long long a, unsigned long long b) {
    unsigned long long r;
    asm("add.rn.f32x2 %0, %1, %2;" : "=l"(r) : "l"(a), "l"(b));
    return r;
}
__device__ __forceinline__ unsigned long long fma2(unsigned long long a, unsigned long long b,
                                                   unsigned long long c) {
    unsigned long long r;
    asm("fma.rn.f32x2 %0, %1, %2, %3;" : "=l"(r) : "l"(a), "l"(b), "l"(c));
    return r;
}
#define ABS2_MASK 0x7FFFFFFF7FFFFFFFULL

// ---------------------------------------------------------------------------
// Kernel A: pi = z @ W1[:128] (+b1), pj = z @ W1[128:]
// 64 blocks x 128 threads; thread = output column d; 16 rows per block.
// Writes row-major AND transposed copies; block 0 also writes g_W2H.
// ---------------------------------------------------------------------------
__global__ void __launch_bounds__(128) prep_kernel(
    const float* __restrict__ z, const float* __restrict__ W1,
    const float* __restrict__ b1, const float* __restrict__ W2)
{
    __shared__ float zs[16][DD];
    const int d  = threadIdx.x;
    const int i0 = blockIdx.x * 16;

    if (blockIdx.x == 0) g_W2H[d] = 0.5f * W2[d];

    for (int idx = d; idx < 16 * DD; idx += 128)
        ((float*)zs)[idx] = z[i0 * DD + idx];
    __syncthreads();

    float api[16], apj[16];
    #pragma unroll
    for (int ii = 0; ii < 16; ii++) { api[ii] = 0.f; apj[ii] = 0.f; }

    #pragma unroll 2
    for (int k = 0; k < DD; k++) {
        const float wpi = __ldg(&W1[k * DD + d]);
        const float wpj = __ldg(&W1[(DD + k) * DD + d]);
        #pragma unroll
        for (int ii = 0; ii < 16; ii++) {
            const float zz = zs[ii][k];
            api[ii] = fmaf(zz, wpi, api[ii]);
            apj[ii] = fmaf(zz, wpj, apj[ii]);
        }
    }

    const float bb = __ldg(&b1[d]);
    #pragma unroll
    for (int ii = 0; ii < 16; ii++) {
        const int i = i0 + ii;
        const float vi = api[ii] + bb;
        const float vj = apj[ii];
        g_PIB [i * DD + d] = vi;
        g_PIBT[d * NN + i] = vi;
        g_PJ  [i * DD + d] = vj;
        g_PJT [d * NN + i] = vj;
    }
}

// ---------------------------------------------------------------------------
// Kernel B: ci[i] = g_PIB[i,:] . g_W2H ; cj[j] = g_PJ[j,:] . g_W2H
// One warp per row: 256 blocks x 256 threads = 2048 warps = 2048 rows.
// ---------------------------------------------------------------------------
__global__ void __launch_bounds__(256) cicj_kernel()
{
    const int warp = blockIdx.x * 8 + (threadIdx.x >> 5);
    const int lane = threadIdx.x & 31;
    const bool is_ci = warp < NN;
    const int  row   = is_ci ? warp : warp - NN;
    const float* src = is_ci ? (g_PIB + row * DD) : (g_PJ + row * DD);

    float4 v = *(const float4*)(src + lane * 4);
    float4 w = *(const float4*)(g_W2H + lane * 4);
    float s = v.x * w.x + v.y * w.y + v.z * w.z + v.w * w.w;
    #pragma unroll
    for (int off = 16; off; off >>= 1)
        s += __shfl_down_sync(0xFFFFFFFFu, s, off);
    if (lane == 0) {
        if (is_ci) g_ci[row] = s; else g_cj[row] = s;
    }
}

// ---------------------------------------------------------------------------
// Kernel C: q[i,j] = ci[i] + cj[j] + sum_d w'_d * |PIBT[d,i] + PJT[d,j]| + b2
// Tile 64i x 64j per block, 256 threads (16x16), 4i x 4j per thread.
// i-pairs packed in f32x2; all inner loads from smem (conflict-free vectors).
// ---------------------------------------------------------------------------
#define TPAD 68   // row stride in floats (64 + 4), keeps 16B alignment

__global__ void __launch_bounds__(256) pair_kernel(
    const float* __restrict__ b2, float* __restrict__ out)
{
    extern __shared__ float smem[];
    float* pisT = smem;                         // [128][TPAD]
    float* pjs  = smem + DD * TPAD;             // [128][TPAD]
    unsigned long long* w2p =
        (unsigned long long*)(smem + 2 * DD * TPAD);  // [128] packed {w',w'}

    const int tx  = threadIdx.x;                // 0..15 -> 4 j
    const int ty  = threadIdx.y;                // 0..15 -> 4 i
    const int tid = ty * 16 + tx;
    const int ib  = blockIdx.y * 64;
    const int jb  = blockIdx.x * 64;

    // Stage tiles: [128 d][64] each, float4 coalesced, conflict-free STS
    for (int idx = tid; idx < DD * 16; idx += 256) {
        const int d = idx >> 4;
        const int q = idx & 15;
        *(float4*)&pisT[d * TPAD + q * 4] =
            *(const float4*)&g_PIBT[d * NN + ib + q * 4];
        *(float4*)&pjs [d * TPAD + q * 4] =
            *(const float4*)&g_PJT [d * NN + jb + q * 4];
    }
    if (tid < DD) {
        const float w = g_W2H[tid];
        w2p[tid] = pack2(w, w);
    }
    __syncthreads();

    const int i0 = ty * 4;                      // local i base
    const int j0 = tx * 4;                      // local j base

    unsigned long long acc[2][4];               // [i-pair][j] ; pair = (i, i+1)
    #pragma unroll
    for (int p = 0; p < 2; p++)
        #pragma unroll
        for (int j = 0; j < 4; j++) acc[p][j] = 0ULL;

    #pragma unroll 4
    for (int d = 0; d < DD; d++) {
        // A: two natural f32x2 pairs {a(i0),a(i0+1)}, {a(i0+2),a(i0+3)}
        const ulonglong2 aA = *(const ulonglong2*)&pisT[d * TPAD + i0];
        // B: 4 j values, broadcast-packed
        const float4 bf = *(const float4*)&pjs[d * TPAD + j0];
        const unsigned long long bp[4] = {
            pack2(bf.x, bf.x), pack2(bf.y, bf.y),
            pack2(bf.z, bf.z), pack2(bf.w, bf.w) };
        const unsigned long long wd = w2p[d];

        #pragma unroll
        for (int j = 0; j < 4; j++) {
            unsigned long long t0 = add2(aA.x, bp[j]) & ABS2_MASK;
            acc[0][j] = fma2(wd, t0, acc[0][j]);
            unsigned long long t1 = add2(aA.y, bp[j]) & ABS2_MASK;
            acc[1][j] = fma2(wd, t1, acc[1][j]);
        }
    }

    // Epilogue: unpack, add rank-1 terms + b2, vector store
    const float4 civ = *(const float4*)&g_ci[ib + i0];
    const float4 cjv = *(const float4*)&g_cj[jb + j0];
    const float  bb  = __ldg(b2);
    const float  cia[4] = { civ.x, civ.y, civ.z, civ.w };
    const float  cja[4] = { cjv.x, cjv.y, cjv.z, cjv.w };

    float v[4][4];                              // [local i][j]
    #pragma unroll
    for (int p = 0; p < 2; p++)
        #pragma unroll
        for (int j = 0; j < 4; j++) {
            float lo, hi;
            unpack2(acc[p][j], lo, hi);
            v[2 * p][j]     = lo;
            v[2 * p + 1][j] = hi;
        }

    #pragma unroll
    for (int r = 0; r < 4; r++) {
        const float base = cia[r] + bb;
        float4 o;
        o.x = v[r][0] + cja[0] + base;
        o.y = v[r][1] + cja[1] + base;
        o.z = v[r][2] + cja[2] + base;
        o.w = v[r][3] + cja[3] + base;
        *(float4*)&out[(ib + i0 + r) * NN + jb + j0] = o;
    }
}

// ---------------------------------------------------------------------------
// metadata order: z [1024*128], W1 [256*128], b1 [128], W2 [128], b2 [1]
// output: float32 [1024*1024]
// ---------------------------------------------------------------------------
extern "C" void kernel_launch(void* const* d_in, const int* in_sizes, int n_in,
                              void* d_out, int out_size)
{
    const float* z  = (const float*)d_in[0];
    const float* W1 = (const float*)d_in[1];
    const float* b1 = (const float*)d_in[2];
    const float* W2 = (const float*)d_in[3];
    const float* b2 = (const float*)d_in[4];
    float* out = (float*)d_out;

    const int smem_bytes = 2 * DD * TPAD * sizeof(float)
                         + DD * sizeof(unsigned long long);
    cudaFuncSetAttribute(pair_kernel,
                         cudaFuncAttributeMaxDynamicSharedMemorySize, smem_bytes);

    prep_kernel<<<NN / 16, 128>>>(z, W1, b1, W2);
    cicj_kernel<<<256, 256>>>();

    dim3 blk(16, 16);
    dim3 grd(NN / 64, NN / 64);
    pair_kernel<<<grd, blk, smem_bytes>>>(b2, out);
}

// round 5
// speedup vs baseline: 1.6846x; 1.3692x over previous
#include <cuda_runtime.h>

#define NN 1024
#define DD 128

// ---------------------------------------------------------------------------
// Device scratch (allocation-free)
// ---------------------------------------------------------------------------
__device__ float g_PIB [NN * DD];   // pi + b1, row-major [i][d]   (for ci)
__device__ float g_PIBT[DD * NN];   // pi + b1, transposed [d][i]  (for pair)
__device__ float g_PJ  [NN * DD];   // pj, row-major [j][d]        (for cj)
__device__ float g_PJT [DD * NN];   // pj, transposed [d][j]       (for pair)
__device__ float g_W2H [DD];        // 0.5 * W2
__device__ float g_ci  [NN];        // 0.5 * PIB[i,:] . W2
__device__ float g_cj  [NN];        // 0.5 * PJ[j,:]  . W2

// ---------------------------------------------------------------------------
// f32x2 packed helpers (sm_103a)
// ---------------------------------------------------------------------------
__device__ __forceinline__ unsigned long long pack2(float lo, float hi) {
    unsigned long long r;
    asm("mov.b64 %0, {%1, %2};" : "=l"(r) : "f"(lo), "f"(hi));
    return r;
}
__device__ __forceinline__ void unpack2(unsigned long long v, float& lo, float& hi) {
    asm("mov.b64 {%0, %1}, %2;" : "=f"(lo), "=f"(hi) : "l"(v));
}
__device__ __forceinline__ unsigned long long add2(unsigned long long a, unsigned long long b) {
    unsigned long long r;
    asm("add.rn.f32x2 %0, %1, %2;" : "=l"(r) : "l"(a), "l"(b));
    return r;
}
__device__ __forceinline__ unsigned long long fma2(unsigned long long a, unsigned long long b,
                                                   unsigned long long c) {
    unsigned long long r;
    asm("fma.rn.f32x2 %0, %1, %2, %3;" : "=l"(r) : "l"(a), "l"(b), "l"(c));
    return r;
}
#define ABS2_MASK 0x7FFFFFFF7FFFFFFFULL

// ---------------------------------------------------------------------------
// Kernel A (rewritten): fused GEMM  C[1024 x 256] = z @ [W1[:128] | W1[128:]]
// 128 blocks x 256 threads. Block = 8 i-rows; thread = one output column dc
// (dc<128 -> pi column, dc>=128 -> pj column) with 8 register accumulators.
// z tile in smem (broadcast LDS); W1 column loads coalesced, unroll-8 MLP.
// The 8 accumulators form a contiguous i-run of the TRANSPOSED array ->
// transpose written free via two STG.128.
// ---------------------------------------------------------------------------
__global__ void __launch_bounds__(256) prep_kernel(
    const float* __restrict__ z, const float* __restrict__ W1,
    const float* __restrict__ b1, const float* __restrict__ W2)
{
    __shared__ float zs[8][DD];
    const int dc = threadIdx.x;          // 0..255 output column
    const int i0 = blockIdx.x * 8;

    if (blockIdx.x == 0 && dc < DD) g_W2H[dc] = 0.5f * W2[dc];

    // Load 8 z rows (1024 floats) with 256 float4 loads
    ((float4*)zs)[dc] = ((const float4*)(z + i0 * DD))[dc];
    __syncthreads();

    const bool is_pi = (dc < DD);
    const int  d     = is_pi ? dc : dc - DD;
    const float* wcol = is_pi ? (W1 + d) : (W1 + DD * DD + d);

    float acc[8];
    #pragma unroll
    for (int ii = 0; ii < 8; ii++) acc[ii] = 0.f;

    #pragma unroll 8
    for (int k = 0; k < DD; k++) {
        const float w = __ldg(&wcol[k * DD]);
        #pragma unroll
        for (int ii = 0; ii < 8; ii++)
            acc[ii] = fmaf(zs[ii][k], w, acc[ii]);
    }

    if (is_pi) {
        const float bb = __ldg(&b1[d]);
        #pragma unroll
        for (int ii = 0; ii < 8; ii++) acc[ii] += bb;
        #pragma unroll
        for (int ii = 0; ii < 8; ii++)
            g_PIB[(i0 + ii) * DD + d] = acc[ii];          // coalesced across dc
        *(float4*)&g_PIBT[d * NN + i0]     = *(float4*)&acc[0];
        *(float4*)&g_PIBT[d * NN + i0 + 4] = *(float4*)&acc[4];
    } else {
        #pragma unroll
        for (int ii = 0; ii < 8; ii++)
            g_PJ[(i0 + ii) * DD + d] = acc[ii];
        *(float4*)&g_PJT[d * NN + i0]     = *(float4*)&acc[0];
        *(float4*)&g_PJT[d * NN + i0 + 4] = *(float4*)&acc[4];
    }
}

// ---------------------------------------------------------------------------
// Kernel B: ci[i] = g_PIB[i,:] . g_W2H ; cj[j] = g_PJ[j,:] . g_W2H
// One warp per row: 256 blocks x 256 threads = 2048 warps = 2048 rows.
// ---------------------------------------------------------------------------
__global__ void __launch_bounds__(256) cicj_kernel()
{
    const int warp = blockIdx.x * 8 + (threadIdx.x >> 5);
    const int lane = threadIdx.x & 31;
    const bool is_ci = warp < NN;
    const int  row   = is_ci ? warp : warp - NN;
    const float* src = is_ci ? (g_PIB + row * DD) : (g_PJ + row * DD);

    float4 v = *(const float4*)(src + lane * 4);
    float4 w = *(const float4*)(g_W2H + lane * 4);
    float s = v.x * w.x + v.y * w.y + v.z * w.z + v.w * w.w;
    #pragma unroll
    for (int off = 16; off; off >>= 1)
        s += __shfl_down_sync(0xFFFFFFFFu, s, off);
    if (lane == 0) {
        if (is_ci) g_ci[row] = s; else g_cj[row] = s;
    }
}

// ---------------------------------------------------------------------------
// Kernel C: q[i,j] = ci[i] + cj[j] + sum_d w'_d * |PIBT[d,i] + PJT[d,j]| + b2
// Tile 64i x 64j per block, 256 threads (16x16), 4i x 4j per thread.
// i-pairs packed in f32x2; all inner loads from smem (conflict-free vectors).
// ---------------------------------------------------------------------------
#define TPAD 68   // row stride in floats (64 + 4), keeps 16B alignment

__global__ void __launch_bounds__(256) pair_kernel(
    const float* __restrict__ b2, float* __restrict__ out)
{
    extern __shared__ float smem[];
    float* pisT = smem;                         // [128][TPAD]
    float* pjs  = smem + DD * TPAD;             // [128][TPAD]
    unsigned long long* w2p =
        (unsigned long long*)(smem + 2 * DD * TPAD);  // [128] packed {w',w'}

    const int tx  = threadIdx.x;                // 0..15 -> 4 j
    const int ty  = threadIdx.y;                // 0..15 -> 4 i
    const int tid = ty * 16 + tx;
    const int ib  = blockIdx.y * 64;
    const int jb  = blockIdx.x * 64;

    // Stage tiles: [128 d][64] each, float4 coalesced, conflict-free STS
    for (int idx = tid; idx < DD * 16; idx += 256) {
        const int d = idx >> 4;
        const int q = idx & 15;
        *(float4*)&pisT[d * TPAD + q * 4] =
            *(const float4*)&g_PIBT[d * NN + ib + q * 4];
        *(float4*)&pjs [d * TPAD + q * 4] =
            *(const float4*)&g_PJT [d * NN + jb + q * 4];
    }
    if (tid < DD) {
        const float w = g_W2H[tid];
        w2p[tid] = pack2(w, w);
    }
    __syncthreads();

    const int i0 = ty * 4;                      // local i base
    const int j0 = tx * 4;                      // local j base

    unsigned long long acc[2][4];               // [i-pair][j] ; pair = (i, i+1)
    #pragma unroll
    for (int p = 0; p < 2; p++)
        #pragma unroll
        for (int j = 0; j < 4; j++) acc[p][j] = 0ULL;

    #pragma unroll 4
    for (int d = 0; d < DD; d++) {
        // A: two natural f32x2 pairs {a(i0),a(i0+1)}, {a(i0+2),a(i0+3)}
        const ulonglong2 aA = *(const ulonglong2*)&pisT[d * TPAD + i0];
        // B: 4 j values, broadcast-packed
        const float4 bf = *(const float4*)&pjs[d * TPAD + j0];
        const unsigned long long bp[4] = {
            pack2(bf.x, bf.x), pack2(bf.y, bf.y),
            pack2(bf.z, bf.z), pack2(bf.w, bf.w) };
        const unsigned long long wd = w2p[d];

        #pragma unroll
        for (int j = 0; j < 4; j++) {
            unsigned long long t0 = add2(aA.x, bp[j]) & ABS2_MASK;
            acc[0][j] = fma2(wd, t0, acc[0][j]);
            unsigned long long t1 = add2(aA.y, bp[j]) & ABS2_MASK;
            acc[1][j] = fma2(wd, t1, acc[1][j]);
        }
    }

    // Epilogue: unpack, add rank-1 terms + b2, vector store
    const float4 civ = *(const float4*)&g_ci[ib + i0];
    const float4 cjv = *(const float4*)&g_cj[jb + j0];
    const float  bb  = __ldg(b2);
    const float  cia[4] = { civ.x, civ.y, civ.z, civ.w };
    const float  cja[4] = { cjv.x, cjv.y, cjv.z, cjv.w };

    float v[4][4];                              // [local i][j]
    #pragma unroll
    for (int p = 0; p < 2; p++)
        #pragma unroll
        for (int j = 0; j < 4; j++) {
            float lo, hi;
            unpack2(acc[p][j], lo, hi);
            v[2 * p][j]     = lo;
            v[2 * p + 1][j] = hi;
        }

    #pragma unroll
    for (int r = 0; r < 4; r++) {
        const float base = cia[r] + bb;
        float4 o;
        o.x = v[r][0] + cja[0] + base;
        o.y = v[r][1] + cja[1] + base;
        o.z = v[r][2] + cja[2] + base;
        o.w = v[r][3] + cja[3] + base;
        *(float4*)&out[(ib + i0 + r) * NN + jb + j0] = o;
    }
}

// ---------------------------------------------------------------------------
// metadata order: z [1024*128], W1 [256*128], b1 [128], W2 [128], b2 [1]
// output: float32 [1024*1024]
// ---------------------------------------------------------------------------
extern "C" void kernel_launch(void* const* d_in, const int* in_sizes, int n_in,
                              void* d_out, int out_size)
{
    const float* z  = (const float*)d_in[0];
    const float* W1 = (const float*)d_in[1];
    const float* b1 = (const float*)d_in[2];
    const float* W2 = (const float*)d_in[3];
    const float* b2 = (const float*)d_in[4];
    float* out = (float*)d_out;

    const int smem_bytes = 2 * DD * TPAD * sizeof(float)
                         + DD * sizeof(unsigned long long);
    cudaFuncSetAttribute(pair_kernel,
                         cudaFuncAttributeMaxDynamicSharedMemorySize, smem_bytes);

    prep_kernel<<<NN / 8, 256>>>(z, W1, b1, W2);
    cicj_kernel<<<256, 256>>>();

    dim3 blk(16, 16);
    dim3 grd(NN / 64, NN / 64);
    pair_kernel<<<grd, blk, smem_bytes>>>(b2, out);
}

// round 6
// speedup vs baseline: 1.7951x; 1.0656x over previous
#include <cuda_runtime.h>

#define NN 1024
#define DD 128

// ---------------------------------------------------------------------------
// Device scratch (allocation-free)
// ---------------------------------------------------------------------------
__device__ float g_PIB [NN * DD];   // pi + b1, row-major [i][d]   (for ci)
__device__ float g_PIBT[DD * NN];   // pi + b1, transposed [d][i]  (for pair)
__device__ float g_PJ  [NN * DD];   // pj, row-major [j][d]        (for cj)
__device__ float g_PJT [DD * NN];   // pj, transposed [d][j]       (for pair)
__device__ float g_W2H [DD];        // 0.5 * W2
__device__ float g_ci  [NN];        // 0.5 * PIB[i,:] . W2
__device__ float g_cj  [NN];        // 0.5 * PJ[j,:]  . W2

// ---------------------------------------------------------------------------
// f32x2 packed helpers (sm_103a)
// ---------------------------------------------------------------------------
__device__ __forceinline__ unsigned long long pack2(float lo, float hi) {
    unsigned long long r;
    asm("mov.b64 %0, {%1, %2};" : "=l"(r) : "f"(lo), "f"(hi));
    return r;
}
__device__ __forceinline__ void unpack2(unsigned long long v, float& lo, float& hi) {
    asm("mov.b64 {%0, %1}, %2;" : "=f"(lo), "=f"(hi) : "l"(v));
}
__device__ __forceinline__ unsigned long long add2(unsigned long long a, unsigned long long b) {
    unsigned long long r;
    asm("add.rn.f32x2 %0, %1, %2;" : "=l"(r) : "l"(a), "l"(b));
    return r;
}
__device__ __forceinline__ unsigned long long fma2(unsigned long long a, unsigned long long b,
                                                   unsigned long long c) {
    unsigned long long r;
    asm("fma.rn.f32x2 %0, %1, %2, %3;" : "=l"(r) : "l"(a), "l"(b), "l"(c));
    return r;
}
#define ABS2_MASK 0x7FFFFFFF7FFFFFFFULL

// ---------------------------------------------------------------------------
// Kernel A (v3): fused GEMM  C[1024 x 256] = z @ [W1[:128] | W1[128:]]
// 128 blocks x 512 threads (16 warps). Block = 8 i-rows.
// Thread = (output column dc = tid&255, row-half h = tid>>8) -> 4 accums.
// k-loop unrolled 16 -> 16 independent W1 loads in flight per thread.
// Same W1 L2 traffic as 128-block version (16 MB), 2x resident warps, 2x MLP.
// Transposed store is a free STG.128 (contiguous 4-row run per thread).
// ---------------------------------------------------------------------------
__global__ void __launch_bounds__(512) prep_kernel(
    const float* __restrict__ z, const float* __restrict__ W1,
    const float* __restrict__ b1, const float* __restrict__ W2)
{
    __shared__ float zs[8][DD];
    const int tid = threadIdx.x;         // 0..511
    const int dc  = tid & 255;           // output column
    const int h   = tid >> 8;            // row half (0/1) -> rows 4h..4h+3
    const int i0  = blockIdx.x * 8;

    if (blockIdx.x == 0 && tid < DD) g_W2H[tid] = 0.5f * W2[tid];

    // Load 8 z rows (1024 floats) with 256 float4 loads
    if (tid < 256)
        ((float4*)zs)[tid] = ((const float4*)(z + i0 * DD))[tid];
    __syncthreads();

    const bool is_pi = (dc < DD);
    const int  d     = is_pi ? dc : dc - DD;
    const float* wcol = is_pi ? (W1 + d) : (W1 + DD * DD + d);
    const int r0 = 4 * h;

    float acc[4] = {0.f, 0.f, 0.f, 0.f};

    #pragma unroll 16
    for (int k = 0; k < DD; k++) {
        const float w = __ldg(&wcol[k * DD]);
        #pragma unroll
        for (int ii = 0; ii < 4; ii++)
            acc[ii] = fmaf(zs[r0 + ii][k], w, acc[ii]);
    }

    if (is_pi) {
        const float bb = __ldg(&b1[d]);
        #pragma unroll
        for (int ii = 0; ii < 4; ii++) acc[ii] += bb;
        #pragma unroll
        for (int ii = 0; ii < 4; ii++)
            g_PIB[(i0 + r0 + ii) * DD + d] = acc[ii];     // coalesced across dc
        *(float4*)&g_PIBT[d * NN + i0 + r0] = *(float4*)&acc[0];
    } else {
        #pragma unroll
        for (int ii = 0; ii < 4; ii++)
            g_PJ[(i0 + r0 + ii) * DD + d] = acc[ii];
        *(float4*)&g_PJT[d * NN + i0 + r0] = *(float4*)&acc[0];
    }
}

// ---------------------------------------------------------------------------
// Kernel B: ci[i] = g_PIB[i,:] . g_W2H ; cj[j] = g_PJ[j,:] . g_W2H
// One warp per row: 256 blocks x 256 threads = 2048 warps = 2048 rows.
// ---------------------------------------------------------------------------
__global__ void __launch_bounds__(256) cicj_kernel()
{
    const int warp = blockIdx.x * 8 + (threadIdx.x >> 5);
    const int lane = threadIdx.x & 31;
    const bool is_ci = warp < NN;
    const int  row   = is_ci ? warp : warp - NN;
    const float* src = is_ci ? (g_PIB + row * DD) : (g_PJ + row * DD);

    float4 v = *(const float4*)(src + lane * 4);
    float4 w = *(const float4*)(g_W2H + lane * 4);
    float s = v.x * w.x + v.y * w.y + v.z * w.z + v.w * w.w;
    #pragma unroll
    for (int off = 16; off; off >>= 1)
        s += __shfl_down_sync(0xFFFFFFFFu, s, off);
    if (lane == 0) {
        if (is_ci) g_ci[row] = s; else g_cj[row] = s;
    }
}

// ---------------------------------------------------------------------------
// Kernel C: q[i,j] = ci[i] + cj[j] + sum_d w'_d * |PIBT[d,i] + PJT[d,j]| + b2
// Tile 64i x 64j per block, 256 threads (16x16), 4i x 4j per thread.
// i-pairs packed in f32x2; all inner loads from smem (conflict-free vectors).
// ---------------------------------------------------------------------------
#define TPAD 68   // row stride in floats (64 + 4), keeps 16B alignment

__global__ void __launch_bounds__(256) pair_kernel(
    const float* __restrict__ b2, float* __restrict__ out)
{
    extern __shared__ float smem[];
    float* pisT = smem;                         // [128][TPAD]
    float* pjs  = smem + DD * TPAD;             // [128][TPAD]
    unsigned long long* w2p =
        (unsigned long long*)(smem + 2 * DD * TPAD);  // [128] packed {w',w'}

    const int tx  = threadIdx.x;                // 0..15 -> 4 j
    const int ty  = threadIdx.y;                // 0..15 -> 4 i
    const int tid = ty * 16 + tx;
    const int ib  = blockIdx.y * 64;
    const int jb  = blockIdx.x * 64;

    // Stage tiles: [128 d][64] each, float4 coalesced, conflict-free STS
    for (int idx = tid; idx < DD * 16; idx += 256) {
        const int d = idx >> 4;
        const int q = idx & 15;
        *(float4*)&pisT[d * TPAD + q * 4] =
            *(const float4*)&g_PIBT[d * NN + ib + q * 4];
        *(float4*)&pjs [d * TPAD + q * 4] =
            *(const float4*)&g_PJT [d * NN + jb + q * 4];
    }
    if (tid < DD) {
        const float w = g_W2H[tid];
        w2p[tid] = pack2(w, w);
    }
    __syncthreads();

    const int i0 = ty * 4;                      // local i base
    const int j0 = tx * 4;                      // local j base

    unsigned long long acc[2][4];               // [i-pair][j] ; pair = (i, i+1)
    #pragma unroll
    for (int p = 0; p < 2; p++)
        #pragma unroll
        for (int j = 0; j < 4; j++) acc[p][j] = 0ULL;

    #pragma unroll 4
    for (int d = 0; d < DD; d++) {
        // A: two natural f32x2 pairs {a(i0),a(i0+1)}, {a(i0+2),a(i0+3)}
        const ulonglong2 aA = *(const ulonglong2*)&pisT[d * TPAD + i0];
        // B: 4 j values, broadcast-packed
        const float4 bf = *(const float4*)&pjs[d * TPAD + j0];
        const unsigned long long bp[4] = {
            pack2(bf.x, bf.x), pack2(bf.y, bf.y),
            pack2(bf.z, bf.z), pack2(bf.w, bf.w) };
        const unsigned long long wd = w2p[d];

        #pragma unroll
        for (int j = 0; j < 4; j++) {
            unsigned long long t0 = add2(aA.x, bp[j]) & ABS2_MASK;
            acc[0][j] = fma2(wd, t0, acc[0][j]);
            unsigned long long t1 = add2(aA.y, bp[j]) & ABS2_MASK;
            acc[1][j] = fma2(wd, t1, acc[1][j]);
        }
    }

    // Epilogue: unpack, add rank-1 terms + b2, vector store
    const float4 civ = *(const float4*)&g_ci[ib + i0];
    const float4 cjv = *(const float4*)&g_cj[jb + j0];
    const float  bb  = __ldg(b2);
    const float  cia[4] = { civ.x, civ.y, civ.z, civ.w };
    const float  cja[4] = { cjv.x, cjv.y, cjv.z, cjv.w };

    float v[4][4];                              // [local i][j]
    #pragma unroll
    for (int p = 0; p < 2; p++)
        #pragma unroll
        for (int j = 0; j < 4; j++) {
            float lo, hi;
            unpack2(acc[p][j], lo, hi);
            v[2 * p][j]     = lo;
            v[2 * p + 1][j] = hi;
        }

    #pragma unroll
    for (int r = 0; r < 4; r++) {
        const float base = cia[r] + bb;
        float4 o;
        o.x = v[r][0] + cja[0] + base;
        o.y = v[r][1] + cja[1] + base;
        o.z = v[r][2] + cja[2] + base;
        o.w = v[r][3] + cja[3] + base;
        *(float4*)&out[(ib + i0 + r) * NN + jb + j0] = o;
    }
}

// ---------------------------------------------------------------------------
// metadata order: z [1024*128], W1 [256*128], b1 [128], W2 [128], b2 [1]
// output: float32 [1024*1024]
// ---------------------------------------------------------------------------
extern "C" void kernel_launch(void* const* d_in, const int* in_sizes, int n_in,
                              void* d_out, int out_size)
{
    const float* z  = (const float*)d_in[0];
    const float* W1 = (const float*)d_in[1];
    const float* b1 = (const float*)d_in[2];
    const float* W2 = (const float*)d_in[3];
    const float* b2 = (const float*)d_in[4];
    float* out = (float*)d_out;

    const int smem_bytes = 2 * DD * TPAD * sizeof(float)
                         + DD * sizeof(unsigned long long);
    cudaFuncSetAttribute(pair_kernel,
                         cudaFuncAttributeMaxDynamicSharedMemorySize, smem_bytes);

    prep_kernel<<<NN / 8, 512>>>(z, W1, b1, W2);
    cicj_kernel<<<256, 256>>>();

    dim3 blk(16, 16);
    dim3 grd(NN / 64, NN / 64);
    pair_kernel<<<grd, blk, smem_bytes>>>(b2, out);
}